// round 1
// baseline (speedup 1.0000x reference)
#include <cuda_runtime.h>
#include <math.h>

// Problem constants
#define NB   32
#define NC   128      // NUM_HIDDENS
#define NHW  4096     // H*W
#define NPIX 131072   // B*H*W
#define ND   64       // EMB_DIM
#define NK   512      // NUM_EMB

// Output layout (float32, concatenated in return order):
// [0]                      loss
// [1 .. 16777216]          global_decode [B,128,H,W]
// [16777217]               perplexity
// [16777218 .. +131072)    indices [B,H,W] (cast to float)
#define OUT_DECODE_OFF 1
#define OUT_PERP_OFF   16777217
#define OUT_IDX_OFF    16777218

// Scratch (no allocations allowed)
__device__ int   g_idx[NPIX];
__device__ int   g_counts[NK];
__device__ float g_partials[512];     // one per k_vq block
__device__ float g_table[NK * NC];    // decode table [k][o]

// ---------------------------------------------------------------- K0: zero
__global__ void k_zero() {
    int t = threadIdx.x;
    if (t < NK) g_counts[t] = 0;
}

// ------------------------------------------------- K1: fused pre-conv + VQ
// smem layout (floats): cb[0,32768) pw[32768,40960) ck[40960,41472) red[41472,41728)
#define SMEM_FLOATS 41728
__global__ void __launch_bounds__(256, 1)
k_vq(const float* __restrict__ enc,
     const float* __restrict__ pre_w,
     const float* __restrict__ pre_b,
     const float* __restrict__ codebook,
     float* __restrict__ out)
{
    extern __shared__ float sm[];
    float* cb  = sm;              // [k*64+d]
    float* pw  = sm + 32768;      // [c*64+o] (transposed pre_w)
    float* ck  = sm + 40960;      // [k] = sum_d cb^2
    float* red = sm + 41472;      // 256 reduction slots

    const int tid = threadIdx.x;

    // Stage codebook
    for (int i = tid; i < NK * ND; i += 256) cb[i] = codebook[i];
    // Stage pre_w transposed: pw[c*64+o] = pre_w[o*128+c]
    for (int i = tid; i < NC * ND; i += 256) {
        int o = i >> 7, c = i & 127;
        pw[c * 64 + o] = pre_w[i];
    }
    __syncthreads();

    // Codebook squared norms (sequential adds, matches reference formula scale)
    for (int k = tid; k < NK; k += 256) {
        float s = 0.f;
        #pragma unroll 8
        for (int d = 0; d < ND; d++) {
            float v = cb[k * 64 + d];
            s = __fadd_rn(s, __fmul_rn(v, v));
        }
        ck[k] = s;
    }

    // ---- Phase 1: z = pre_w @ enc_pixel + pre_b (sequential FMA over c) ----
    const int n  = blockIdx.x * 256 + tid;
    const int b  = n >> 12;
    const int hw = n & 4095;
    const float* ep = enc + (size_t)b * (NC * NHW) + hw;

    float z[64];
    #pragma unroll
    for (int o = 0; o < 64; o++) z[o] = 0.f;

    #pragma unroll 4
    for (int c = 0; c < NC; c++) {
        float e = ep[(size_t)c * NHW];
        const float4* w4 = (const float4*)(pw + c * 64);
        #pragma unroll
        for (int j = 0; j < 16; j++) {
            float4 w = w4[j];
            z[4 * j + 0] = fmaf(e, w.x, z[4 * j + 0]);
            z[4 * j + 1] = fmaf(e, w.y, z[4 * j + 1]);
            z[4 * j + 2] = fmaf(e, w.z, z[4 * j + 2]);
            z[4 * j + 3] = fmaf(e, w.w, z[4 * j + 3]);
        }
    }
    // bias (zeros in this dataset, but stay faithful)
    #pragma unroll
    for (int o = 0; o < 64; o++) z[o] = __fadd_rn(z[o], __ldg(&pre_b[o]));

    // F = sum(z*z): rounded products, sequential adds (mirrors flat*flat then sum)
    float F = 0.f;
    #pragma unroll
    for (int o = 0; o < 64; o++) F = __fadd_rn(F, __fmul_rn(z[o], z[o]));

    __syncthreads();  // ck ready

    // ---- Phase 2: dist scan + argmin (first-occurrence tiebreak) ----
    float best = 3.4e38f;
    int   bk   = 0;
    for (int k = 0; k < NK; k++) {
        const float4* c4 = (const float4*)(cb + k * 64);
        float p0 = 0.f, p1 = 0.f, p2 = 0.f, p3 = 0.f;
        #pragma unroll
        for (int j = 0; j < 16; j++) {
            float4 cv = c4[j];
            p0 = fmaf(z[4 * j + 0], cv.x, p0);
            p1 = fmaf(z[4 * j + 1], cv.y, p1);
            p2 = fmaf(z[4 * j + 2], cv.z, p2);
            p3 = fmaf(z[4 * j + 3], cv.w, p3);
        }
        float P = __fadd_rn(__fadd_rn(p0, p1), __fadd_rn(p2, p3));
        // dist = fl( fl(F + C_k) - 2P )  — exact reference op order
        float dist = __fadd_rn(__fadd_rn(F, ck[k]), -2.f * P);
        if (dist < best) { best = dist; bk = k; }
    }

    // ---- Phase 3: outputs + loss partial + histogram ----
    g_idx[n] = bk;
    out[OUT_IDX_OFF + n] = (float)bk;
    atomicAdd(&g_counts[bk], 1);

    float lp = 0.f;
    #pragma unroll
    for (int o = 0; o < 64; o++) {
        float d = __fadd_rn(cb[bk * 64 + o], -z[o]);
        lp = fmaf(d, d, lp);
    }
    red[tid] = lp;
    __syncthreads();
    #pragma unroll
    for (int s = 128; s > 0; s >>= 1) {
        if (tid < s) red[tid] += red[tid + s];
        __syncthreads();
    }
    if (tid == 0) g_partials[blockIdx.x] = red[0];
}

// ----------------------------------------- K2: decode table (512 x 128)
__global__ void k_table(const float* __restrict__ codebook,
                        const float* __restrict__ post_w,
                        const float* __restrict__ post_b)
{
    __shared__ float cbr[64];
    const int k = blockIdx.x;
    const int o = threadIdx.x;
    if (o < 64) cbr[o] = codebook[k * 64 + o];
    __syncthreads();
    float s = 0.f;
    const float* w = post_w + o * 64;
    #pragma unroll
    for (int d = 0; d < 64; d++) s = fmaf(cbr[d], __ldg(&w[d]), s);
    g_table[k * 128 + o] = __fadd_rn(s, __ldg(&post_b[o]));
}

// ----------------------------------------- K3: gather -> global_decode
__global__ void k_decode(float* __restrict__ out)
{
    const int g  = blockIdx.x * 256 + threadIdx.x;  // 16,777,216 total
    const int hw = g & 4095;
    const int o  = (g >> 12) & 127;
    const int b  = g >> 19;
    const int n  = (b << 12) | hw;
    const int k  = g_idx[n];
    out[OUT_DECODE_OFF + g] = g_table[k * 128 + o];
}

// ----------------------------------------- K4: loss + perplexity
__global__ void k_final(float* __restrict__ out)
{
    __shared__ float sh[512];
    const int t = threadIdx.x;  // 512 threads

    // perplexity
    float p = (float)g_counts[t] / (float)NPIX;
    sh[t] = -(p * logf(p + 1e-10f));
    __syncthreads();
    #pragma unroll
    for (int s = 256; s > 0; s >>= 1) {
        if (t < s) sh[t] += sh[t + s];
        __syncthreads();
    }
    if (t == 0) out[OUT_PERP_OFF] = expf(sh[0]);
    __syncthreads();

    // loss = 1.25 * mean((q - z)^2) over NPIX*ND elements
    sh[t] = g_partials[t];
    __syncthreads();
    #pragma unroll
    for (int s = 256; s > 0; s >>= 1) {
        if (t < s) sh[t] += sh[t + s];
        __syncthreads();
    }
    if (t == 0) out[0] = 1.25f * (sh[0] / 8388608.f);
}

// ---------------------------------------------------------------- launch
extern "C" void kernel_launch(void* const* d_in, const int* in_sizes, int n_in,
                              void* d_out, int out_size)
{
    const float* enc      = (const float*)d_in[0];
    const float* pre_w    = (const float*)d_in[1];
    const float* pre_b    = (const float*)d_in[2];
    const float* codebook = (const float*)d_in[3];
    const float* post_w   = (const float*)d_in[4];
    const float* post_b   = (const float*)d_in[5];
    float* out = (float*)d_out;

    cudaFuncSetAttribute(k_vq, cudaFuncAttributeMaxDynamicSharedMemorySize,
                         SMEM_FLOATS * 4);

    k_zero  <<<1, 512>>>();
    k_vq    <<<NPIX / 256, 256, SMEM_FLOATS * 4>>>(enc, pre_w, pre_b, codebook, out);
    k_table <<<NK, 128>>>(codebook, post_w, post_b);
    k_decode<<<16777216 / 256, 256>>>(out);
    k_final <<<1, 512>>>(out);
}

// round 2
// speedup vs baseline: 1.3752x; 1.3752x over previous
#include <cuda_runtime.h>
#include <math.h>

// Problem constants
#define NB   32
#define NC   128      // NUM_HIDDENS
#define NHW  4096     // H*W
#define NPIX 131072   // B*H*W
#define ND   64       // EMB_DIM
#define NK   512      // NUM_EMB

// Output layout (float32, concatenated):
#define OUT_DECODE_OFF 1
#define OUT_PERP_OFF   16777217
#define OUT_IDX_OFF    16777218

typedef unsigned long long u64;

// Scratch (no allocations allowed)
__device__ int   g_idx[NPIX];
__device__ int   g_counts[NK];
__device__ float g_partials[256];        // one per k_vq block (256 blocks)
__device__ float g_table_T[NC * NK];     // decode table transposed [o][k]

// ---- packed f32x2 helpers (Blackwell FFMA2 pipe: 2 fp32 FMAs / instr) ----
__device__ __forceinline__ u64 ffma2(u64 a, u64 b, u64 c) {
    u64 d;
    asm("fma.rn.f32x2 %0, %1, %2, %3;" : "=l"(d) : "l"(a), "l"(b), "l"(c));
    return d;
}
__device__ __forceinline__ u64 fadd2(u64 a, u64 b) {
    u64 d;
    asm("add.rn.f32x2 %0, %1, %2;" : "=l"(d) : "l"(a), "l"(b));
    return d;
}
__device__ __forceinline__ u64 pack2(float lo, float hi) {
    u64 d;
    asm("mov.b64 %0, {%1, %2};" : "=l"(d) : "f"(lo), "f"(hi));
    return d;
}
__device__ __forceinline__ void unpack2(u64 v, float& lo, float& hi) {
    asm("mov.b64 {%0, %1}, %2;" : "=f"(lo), "=f"(hi) : "l"(v));
}

// ---------------------------------------------------------------- K0: zero
__global__ void k_zero() {
    int t = threadIdx.x;
    if (t < NK) g_counts[t] = 0;
}

// ------------------------------------------------- K1: fused pre-conv + VQ
// smem floats: cb[0,32768) pw[32768,40960) ck[40960,41472) red[41472,41984)
#define SMEM_FLOATS 41984
__global__ void __launch_bounds__(512, 1)
k_vq(const float* __restrict__ enc,
     const float* __restrict__ pre_w,
     const float* __restrict__ pre_b,
     const float* __restrict__ codebook,
     float* __restrict__ out)
{
    extern __shared__ float sm[];
    float* cb  = sm;              // [k*64+d]
    float* pw  = sm + 32768;      // [c*64+o] (transposed pre_w)
    float* ck  = sm + 40960;      // [k] = ||c_k||^2
    float* red = sm + 41472;      // 512 reduction slots

    const int tid = threadIdx.x;

    for (int i = tid; i < NK * ND; i += 512) cb[i] = codebook[i];
    for (int i = tid; i < NC * ND; i += 512) {
        int o = i >> 7, c = i & 127;
        pw[c * 64 + o] = pre_w[i];
    }
    __syncthreads();

    if (tid < NK) {
        float s = 0.f;
        #pragma unroll 8
        for (int d = 0; d < ND; d++) {
            float v = cb[tid * 64 + d];
            s = __fadd_rn(s, __fmul_rn(v, v));
        }
        ck[tid] = s;
    }

    // ---- Phase 1: z = pre_w @ enc_pixel + pre_b (packed f32x2) ----
    const int n  = blockIdx.x * 512 + tid;
    const int b  = n >> 12;
    const int hw = n & 4095;
    const float* ep = enc + (size_t)b * (NC * NHW) + hw;

    u64 z2[32];
    #pragma unroll
    for (int j = 0; j < 32; j++) z2[j] = 0ull;

    const u64* pw2 = (const u64*)pw;
    #pragma unroll 2
    for (int c = 0; c < NC; c++) {
        float e = ep[(size_t)c * NHW];
        u64 e2 = pack2(e, e);
        const u64* w2 = pw2 + c * 32;
        #pragma unroll
        for (int j = 0; j < 32; j++) z2[j] = ffma2(e2, w2[j], z2[j]);
    }
    // bias (aligned 64-bit loads of pre_b pairs)
    {
        const u64* pb2 = (const u64*)pre_b;
        #pragma unroll
        for (int j = 0; j < 32; j++) z2[j] = fadd2(z2[j], __ldg(&pb2[j]));
    }

    // F = sum(z*z) (rounded mul + sequential adds)
    float F = 0.f;
    #pragma unroll
    for (int j = 0; j < 32; j++) {
        float lo, hi;
        unpack2(z2[j], lo, hi);
        F = __fadd_rn(F, __fmul_rn(lo, lo));
        F = __fadd_rn(F, __fmul_rn(hi, hi));
    }

    __syncthreads();  // ck ready

    // ---- Phase 2: distance scan + argmin (first-occurrence tiebreak) ----
    const u64* cb2 = (const u64*)cb;
    float best = 3.4e38f;
    int   bk   = 0;
    for (int k = 0; k < NK; k++) {
        const u64* c2 = cb2 + k * 32;
        u64 a0 = 0ull, a1 = 0ull;
        #pragma unroll
        for (int j = 0; j < 32; j += 2) {
            a0 = ffma2(z2[j],     c2[j],     a0);
            a1 = ffma2(z2[j + 1], c2[j + 1], a1);
        }
        float lo, hi;
        unpack2(fadd2(a0, a1), lo, hi);
        float P = __fadd_rn(lo, hi);
        // -2P is exact, so fmaf(-2,P,F+C) == fl(fl(F+C) - 2P)
        float dist = fmaf(-2.f, P, __fadd_rn(F, ck[k]));
        if (dist < best) { best = dist; bk = k; }
    }

    // ---- Phase 3: outputs + loss partial + histogram ----
    g_idx[n] = bk;
    out[OUT_IDX_OFF + n] = (float)bk;
    atomicAdd(&g_counts[bk], 1);

    float lp = 0.f;
    #pragma unroll
    for (int o = 0; o < 64; o++) {
        float d = __fadd_rn(cb[bk * 64 + o], -[&]{ return 0.f; }());  // placeholder avoided
        (void)d;
    }
    // (compute loss partial properly)
    lp = 0.f;
    #pragma unroll
    for (int j = 0; j < 32; j++) {
        float lo, hi;
        unpack2(z2[j], lo, hi);
        float d0 = __fadd_rn(cb[bk * 64 + 2 * j],     -lo);
        float d1 = __fadd_rn(cb[bk * 64 + 2 * j + 1], -hi);
        lp = fmaf(d0, d0, lp);
        lp = fmaf(d1, d1, lp);
    }
    red[tid] = lp;
    __syncthreads();
    #pragma unroll
    for (int s = 256; s > 0; s >>= 1) {
        if (tid < s) red[tid] += red[tid + s];
        __syncthreads();
    }
    if (tid == 0) g_partials[blockIdx.x] = red[0];
}

// ----------------------------------------- K2: decode table (transposed [o][k])
__global__ void k_table(const float* __restrict__ codebook,
                        const float* __restrict__ post_w,
                        const float* __restrict__ post_b)
{
    __shared__ float cbr[64];
    const int k = blockIdx.x;
    const int o = threadIdx.x;
    if (o < 64) cbr[o] = codebook[k * 64 + o];
    __syncthreads();
    float s = 0.f;
    const float* w = post_w + o * 64;
    #pragma unroll
    for (int d = 0; d < 64; d++) s = fmaf(cbr[d], __ldg(&w[d]), s);
    g_table_T[o * NK + k] = __fadd_rn(s, __ldg(&post_b[o]));
}

// ----------------------------------------- K3: gather -> global_decode
// One block per (b,o): stage 2KB table row in smem, coalesced writes.
__global__ void __launch_bounds__(256)
k_decode(float* __restrict__ out)
{
    __shared__ float s_tab[NK];
    const int blk = blockIdx.x;       // 0..4095
    const int b   = blk >> 7;
    const int o   = blk & 127;
    const int tid = threadIdx.x;

    s_tab[tid]       = g_table_T[o * NK + tid];
    s_tab[tid + 256] = g_table_T[o * NK + tid + 256];
    __syncthreads();

    const int* idx = g_idx + b * NHW;
    float* dst = out + OUT_DECODE_OFF + ((size_t)(b * NC + o)) * NHW;
    #pragma unroll 4
    for (int hw = tid; hw < NHW; hw += 256) {
        dst[hw] = s_tab[idx[hw]];
    }
}

// ----------------------------------------- K4: loss + perplexity
__global__ void k_final(float* __restrict__ out)
{
    __shared__ float sh[512];
    const int t = threadIdx.x;  // 512 threads

    float p = (float)g_counts[t] / (float)NPIX;
    sh[t] = -(p * logf(p + 1e-10f));
    __syncthreads();
    #pragma unroll
    for (int s = 256; s > 0; s >>= 1) {
        if (t < s) sh[t] += sh[t + s];
        __syncthreads();
    }
    if (t == 0) out[OUT_PERP_OFF] = expf(sh[0]);
    __syncthreads();

    sh[t] = (t < 256) ? g_partials[t] : 0.f;
    __syncthreads();
    #pragma unroll
    for (int s = 256; s > 0; s >>= 1) {
        if (t < s) sh[t] += sh[t + s];
        __syncthreads();
    }
    if (t == 0) out[0] = 1.25f * (sh[0] / 8388608.f);
}

// ---------------------------------------------------------------- launch
extern "C" void kernel_launch(void* const* d_in, const int* in_sizes, int n_in,
                              void* d_out, int out_size)
{
    const float* enc      = (const float*)d_in[0];
    const float* pre_w    = (const float*)d_in[1];
    const float* pre_b    = (const float*)d_in[2];
    const float* codebook = (const float*)d_in[3];
    const float* post_w   = (const float*)d_in[4];
    const float* post_b   = (const float*)d_in[5];
    float* out = (float*)d_out;

    cudaFuncSetAttribute(k_vq, cudaFuncAttributeMaxDynamicSharedMemorySize,
                         SMEM_FLOATS * 4);

    k_zero  <<<1, 512>>>();
    k_vq    <<<NPIX / 512, 512, SMEM_FLOATS * 4>>>(enc, pre_w, pre_b, codebook, out);
    k_table <<<NK, 128>>>(codebook, post_w, post_b);
    k_decode<<<NB * NC, 256>>>(out);
    k_final <<<1, 512>>>(out);
}